// round 10
// baseline (speedup 1.0000x reference)
#include <cuda_runtime.h>

// Problem constants
#define BB 16
#define NN 4096
#define SS 1024
#define KK 32
#define PTOT (BB*SS*KK)      // 524288 positions
#define C0 67
#define C1 64
#define C3 128

typedef unsigned long long u64;

// ---------------- device scratch (no allocation allowed) ----------------
__device__ float g_newxyz[BB*SS*3];
__device__ float g_ptsT[(size_t)BB*NN*64];   // 16MB  [b][n][c]
__device__ float g_bufA[(size_t)PTOT*128];   // 256MB
__device__ float g_bufB[(size_t)PTOT*128];   // 256MB (L3: reused as max/min buffers)
__device__ float g_psum[128*4096];
__device__ float g_psq[128*4096];
__device__ float g_scale[128];
__device__ float g_shift[128];
__device__ float g_wt0[C0*C1];
__device__ float g_wt1[C1*C1];
__device__ float g_wt2[C1*C3];
__device__ int   g_flag[BB];                 // fps done per batch
__device__ int   g_tdone;                    // transpose barrier

// ---------------- f32x2 helpers ----------------
__device__ __forceinline__ u64 pk2(float x, float y) {
    u64 r; asm("mov.b64 %0, {%1,%2};" : "=l"(r) : "f"(x), "f"(y)); return r;
}
__device__ __forceinline__ void upk2(u64 v, float& x, float& y) {
    asm("mov.b64 {%0,%1}, %2;" : "=f"(x), "=f"(y) : "l"(v));
}
__device__ __forceinline__ void ffma2(u64& d, u64 a, u64 b) {
    asm("fma.rn.f32x2 %0, %1, %2, %0;" : "+l"(d) : "l"(a), "l"(b));
}
// bank-conflict swizzle: XOR 16B-chunk index with 128B-row index (within 1KB window)
__device__ __forceinline__ unsigned swz(unsigned byteoff) {
    return byteoff ^ ((byteoff >> 3) & 0x70u);
}

__device__ __forceinline__ float sqdist_exact(float dx, float dy, float dz) {
    return __fadd_rn(__fadd_rn(__fmul_rn(dx, dx), __fmul_rn(dy, dy)), __fmul_rn(dz, dz));
}

// =======================================================================
// 0) reset flags (must run every replay)
// =======================================================================
__global__ void reset_kernel() {
    int t = threadIdx.x;
    if (t < BB) g_flag[t] = 0;
    if (t == BB) g_tdone = 0;
}

// =======================================================================
// 1) MEGA front-end kernel: 144 blocks x 1024 threads, all resident.
// =======================================================================
extern __shared__ float smd[];

__global__ __launch_bounds__(1024) void mega_kernel(const float* __restrict__ xyz,
                                                    const float* __restrict__ pts,
                                                    float* __restrict__ ptsT,
                                                    float* __restrict__ feat) {
    const int t = threadIdx.x;
    const int w = t >> 5, lane = t & 31;

    if (blockIdx.x < BB) {
        // ---------------- FPS ----------------
        int b = blockIdx.x;
        for (int i = t; i < 3*NN; i += 1024)
            smd[i] = xyz[(size_t)b*3*NN + i];
        __syncthreads();

        float4 X = ((const float4*)smd)[t];
        float4 Y = ((const float4*)(smd + NN))[t];
        float4 Z = ((const float4*)(smd + 2*NN))[t];
        float d0 = 1e10f, d1 = 1e10f, d2 = 1e10f, d3 = 1e10f;

        unsigned* sv = (unsigned*)(smd + 3*NN);
        int*      si = (int*)(smd + 3*NN + 32);
        int*      sfar = (int*)(smd + 3*NN + 64);

        int far = 0;
        for (int s = 0; s < SS; s++) {
            float cx = smd[far], cy = smd[NN + far], cz = smd[2*NN + far];
            if (t == 0) {
                g_newxyz[(b*SS + s)*3 + 0] = cx;
                g_newxyz[(b*SS + s)*3 + 1] = cy;
                g_newxyz[(b*SS + s)*3 + 2] = cz;
            }
            d0 = fminf(d0, sqdist_exact(X.x - cx, Y.x - cy, Z.x - cz));
            d1 = fminf(d1, sqdist_exact(X.y - cx, Y.y - cy, Z.y - cz));
            d2 = fminf(d2, sqdist_exact(X.z - cx, Y.z - cy, Z.z - cz));
            d3 = fminf(d3, sqdist_exact(X.w - cx, Y.w - cy, Z.w - cz));

            float bv = d0; int bi = 4*t;
            if (d1 > bv) { bv = d1; bi = 4*t + 1; }
            if (d2 > bv) { bv = d2; bi = 4*t + 2; }
            if (d3 > bv) { bv = d3; bi = 4*t + 3; }

            unsigned key = __float_as_uint(bv);
            unsigned wm = __reduce_max_sync(0xffffffffu, key);
            unsigned mm = __ballot_sync(0xffffffffu, key == wm);
            int ln = __ffs(mm) - 1;
            int wbi = __shfl_sync(0xffffffffu, bi, ln);
            if (lane == 0) { sv[w] = wm; si[w] = wbi; }
            __syncthreads();
            if (t < 32) {
                unsigned k2 = sv[t]; int i2 = si[t];
                unsigned wm2 = __reduce_max_sync(0xffffffffu, k2);
                unsigned m2 = __ballot_sync(0xffffffffu, k2 == wm2);
                int l2 = __ffs(m2) - 1;
                int f2 = __shfl_sync(0xffffffffu, i2, l2);
                if (t == 0) *sfar = f2;
            }
            __syncthreads();
            far = *sfar;
        }
        __threadfence();
        if (t == 0) atomicExch(&g_flag[b], 1);
        return;
    }

    // ---------------- workers ----------------
    int wb = blockIdx.x - BB;          // 0..127
    int b = wb >> 3, sub = wb & 7;

    // Phase A: pts transpose share (32 tiles of 32x32)
    {
        float* tile = smd;
        for (int tix = wb*32; tix < wb*32 + 32; tix++) {
            int tb = tix >> 8, rem = tix & 255;
            int ct = rem >> 7, nt = rem & 127;
            tile[lane*33 + w] = pts[((size_t)tb*64 + ct*32 + w)*NN + nt*32 + lane];
            __syncthreads();
            ptsT[((size_t)tb*NN + nt*32 + w)*64 + ct*32 + lane] = tile[w*33 + lane];
            __syncthreads();
        }
        __threadfence();
        if (t == 0) atomicAdd(&g_tdone, 1);
    }
    if (t == 0) { while (atomicAdd(&g_tdone, 0) < 128) __nanosleep(128); }
    if (t == 0) { while (atomicAdd(&g_flag[b], 0) == 0) __nanosleep(256); }
    __syncthreads();
    __threadfence();

    for (int i = t; i < 3*NN; i += 1024)
        smd[i] = xyz[(size_t)b*3*NN + i];
    __syncthreads();

    int* sIdx = (int*)(smd + 3*NN);

    for (int r = 0; r < 4; r++) {
        int bs = b*1024 + sub*128 + w*4 + r;
        float cx = g_newxyz[bs*3], cy = g_newxyz[bs*3 + 1], cz = g_newxyz[bs*3 + 2];
        float snew = cx*cx + cy*cy + cz*cz;
        int cnt = 0, first = -1;
        for (int n0 = 0; n0 < NN && cnt < KK; n0 += 32) {
            int n = n0 + lane;
            float px = smd[n], py = smd[NN + n], pz = smd[2*NN + n];
            float sp = px*px + py*py + pz*pz;
            float d = snew + sp - 2.0f*(cx*px + cy*py + cz*pz);
            bool in = (d <= 0.04f);
            unsigned m = __ballot_sync(0xffffffffu, in);
            if (first < 0 && m) first = n0 + __ffs(m) - 1;
            int rank = __popc(m & ((1u << lane) - 1u));
            if (in && cnt + rank < KK) sIdx[w*32 + cnt + rank] = n;
            cnt += __popc(m);
        }
        if (lane >= cnt) sIdx[w*32 + lane] = first;
        __syncwarp();

        int n = sIdx[w*32 + lane];
        #pragma unroll
        for (int c = 0; c < 3; c++)
            feat[(size_t)c*PTOT + bs*KK + lane] = smd[c*NN + n] - g_newxyz[bs*3 + c];
        const float4* row = (const float4*)(ptsT + ((size_t)b*NN + n)*64);
        #pragma unroll
        for (int c4 = 0; c4 < 16; c4++) {
            float4 v = row[c4];
            feat[(size_t)(3 + 4*c4 + 0)*PTOT + bs*KK + lane] = v.x;
            feat[(size_t)(3 + 4*c4 + 1)*PTOT + bs*KK + lane] = v.y;
            feat[(size_t)(3 + 4*c4 + 2)*PTOT + bs*KK + lane] = v.z;
            feat[(size_t)(3 + 4*c4 + 3)*PTOT + bs*KK + lane] = v.w;
        }
        __syncwarp();
    }
}

// =======================================================================
// 2) All three weight transposes in one launch: wt[k][m] = W[m][k]
// =======================================================================
__global__ void wtrans_all_kernel(const float* __restrict__ w0,
                                  const float* __restrict__ w1,
                                  const float* __restrict__ w2) {
    int i = blockIdx.x * 256 + threadIdx.x;
    if (i < C0*C1) {
        int k = i / C1, m = i - k*C1;
        g_wt0[i] = w0[m*C0 + k];
    } else if (i < C0*C1 + C1*C1) {
        int j = i - C0*C1, k = j / C1, m = j - k*C1;
        g_wt1[j] = w1[m*C1 + k];
    } else if (i < C0*C1 + C1*C1 + C1*C3) {
        int j = i - C0*C1 - C1*C1, k = j / C3, m = j - k*C3;
        g_wt2[j] = w2[m*C1 + k];
    }
}

// =======================================================================
// 3) GEMM: out[M][PTOT] = Wt^T x in[K][PTOT] (+bias).
//    Thread tile 8x16, block tile Mx256, THREADS = 2*M (128 or 256).
//    sA XOR-swizzled. Optional BN+ReLU on load. Per-block BN partials.
//    POOL: emit per-(m, centroid) max/min instead of storing activations
//    (NT=256 -> 8 centroids of K=32 per block).
// =======================================================================
extern __shared__ float smg[];

template<int M, int K, bool BN, bool POOL>
__global__ __launch_bounds__(2*M) void gemm_kernel(const float* __restrict__ in,
                                                   float* __restrict__ out,
                                                   const float* __restrict__ wt,
                                                   const float* __restrict__ bias,
                                                   float* __restrict__ psum,
                                                   float* __restrict__ psq,
                                                   int nblk) {
    constexpr int TM = 8;
    constexpr int TN = 16;
    constexpr int NT = 256;
    constexpr int THREADS = 2*M;
    float* sW = smg;                   // K*M
    char*  sAb = (char*)(smg + K*M);   // K*NT floats, swizzled
    const int t = threadIdx.x;
    const int tn = t & 15, tm = t >> 4;
    const int n0 = blockIdx.x * NT;

    for (int i = t; i < K*M; i += THREADS) sW[i] = wt[i];
    for (int i = t; i < K*(NT/4); i += THREADS) {
        int k = i / (NT/4), c = (i % (NT/4)) << 2;
        float4 v = *(const float4*)(in + (size_t)k*PTOT + n0 + c);
        if (BN) {
            float sc = g_scale[k], sh = g_shift[k];
            v.x = fmaxf(fmaf(v.x, sc, sh), 0.0f);
            v.y = fmaxf(fmaf(v.y, sc, sh), 0.0f);
            v.z = fmaxf(fmaf(v.z, sc, sh), 0.0f);
            v.w = fmaxf(fmaf(v.w, sc, sh), 0.0f);
        }
        *(float4*)(sAb + swz((unsigned)(k*NT + c)*4u)) = v;
    }
    __syncthreads();

    u64 acc[TM][TN/2];
    #pragma unroll
    for (int j = 0; j < TM; j++)
        #pragma unroll
        for (int q = 0; q < TN/2; q++) acc[j][q] = 0ull;

    #pragma unroll 2
    for (int k = 0; k < K; k++) {
        u64 av[TN/2];
        #pragma unroll
        for (int q = 0; q < TN/4; q++) {
            ulonglong2 tmp = *(const ulonglong2*)(sAb + swz((unsigned)(k*NT + tn*TN + q*4)*4u));
            av[q*2] = tmp.x; av[q*2 + 1] = tmp.y;
        }
        #pragma unroll
        for (int j = 0; j < TM; j += 4) {
            float4 wv = *(const float4*)(sW + k*M + tm*TM + j);
            u64 w0 = pk2(wv.x, wv.x);
            u64 w1 = pk2(wv.y, wv.y);
            u64 w2 = pk2(wv.z, wv.z);
            u64 w3 = pk2(wv.w, wv.w);
            #pragma unroll
            for (int q = 0; q < TN/2; q++) ffma2(acc[j+0][q], av[q], w0);
            #pragma unroll
            for (int q = 0; q < TN/2; q++) ffma2(acc[j+1][q], av[q], w1);
            #pragma unroll
            for (int q = 0; q < TN/2; q++) ffma2(acc[j+2][q], av[q], w2);
            #pragma unroll
            for (int q = 0; q < TN/2; q++) ffma2(acc[j+3][q], av[q], w3);
        }
    }

    // epilogue: bias, (store | pool), partial stats
    float ps[TM], pq[TM], pmx[TM], pmn[TM];
    #pragma unroll
    for (int j = 0; j < TM; j++) {
        int m = tm*TM + j;
        float bsv = bias[m];
        float vals[TN];
        #pragma unroll
        for (int q = 0; q < TN/2; q++) {
            float x, y; upk2(acc[j][q], x, y);
            vals[2*q] = x + bsv; vals[2*q + 1] = y + bsv;
        }
        if (!POOL) {
            #pragma unroll
            for (int q = 0; q < TN/4; q++)
                *(float4*)(out + (size_t)m*PTOT + n0 + tn*TN + q*4) =
                    make_float4(vals[4*q], vals[4*q+1], vals[4*q+2], vals[4*q+3]);
        }
        float s = 0.0f, q2 = 0.0f, mx = -3.4e38f, mn = 3.4e38f;
        #pragma unroll
        for (int p = 0; p < TN; p++) {
            s += vals[p]; q2 = fmaf(vals[p], vals[p], q2);
            if (POOL) { mx = fmaxf(mx, vals[p]); mn = fminf(mn, vals[p]); }
        }
        ps[j] = s; pq[j] = q2; pmx[j] = mx; pmn[j] = mn;
    }
    __syncthreads();
    float* red = (float*)sAb;        // M*16 sums, M*16 sq [, M*16 max, M*16 min]
    #pragma unroll
    for (int j = 0; j < TM; j++) {
        int m = tm*TM + j;
        red[m*16 + tn] = ps[j];
        red[M*16 + m*16 + tn] = pq[j];
        if (POOL) {
            red[2*M*16 + m*16 + tn] = pmx[j];
            red[3*M*16 + m*16 + tn] = pmn[j];
        }
    }
    __syncthreads();
    if (t < M) {
        float s = 0.0f, q2 = 0.0f;
        #pragma unroll
        for (int i = 0; i < 16; i++) { s += red[t*16 + i]; q2 += red[M*16 + t*16 + i]; }
        psum[(size_t)t*nblk + blockIdx.x] = s;
        psq [(size_t)t*nblk + blockIdx.x] = q2;
    }
    if (POOL) {
        // 8 centroids per block (NT=256, K=32); centroid g covers tn = 2g, 2g+1
        for (int p = t; p < 8*M; p += THREADS) {
            int m = p >> 3, g = p & 7;
            float mx = fmaxf(red[2*M*16 + m*16 + 2*g], red[2*M*16 + m*16 + 2*g + 1]);
            float mn = fminf(red[3*M*16 + m*16 + 2*g], red[3*M*16 + m*16 + 2*g + 1]);
            int bsg = blockIdx.x*8 + g;
            out[(size_t)m*(BB*SS) + bsg] = mx;
            out[(size_t)C3*(BB*SS) + (size_t)m*(BB*SS) + bsg] = mn;
        }
    }
}

// =======================================================================
// 4) Reduce partials -> BN scale/shift
// =======================================================================
__global__ __launch_bounds__(256) void reduce_stats_kernel(const float* __restrict__ psum,
                                                           const float* __restrict__ psq,
                                                           const float* __restrict__ g,
                                                           const float* __restrict__ bt,
                                                           int nblk) {
    int c = blockIdx.x, t = threadIdx.x;
    float s = 0.0f, q = 0.0f;
    for (int i = t; i < nblk; i += 256) {
        s += psum[(size_t)c*nblk + i];
        q += psq [(size_t)c*nblk + i];
    }
    __shared__ float ss[256], sq[256];
    ss[t] = s; sq[t] = q;
    __syncthreads();
    for (int o = 128; o; o >>= 1) {
        if (t < o) { ss[t] += ss[t + o]; sq[t] += sq[t + o]; }
        __syncthreads();
    }
    if (t == 0) {
        float mu  = ss[0] / (float)PTOT;
        float var = sq[0] / (float)PTOT - mu * mu;
        float sc  = rsqrtf(var + 1e-5f) * g[c];
        g_scale[c] = sc;
        g_shift[c] = bt[c] - mu * sc;
    }
}

// =======================================================================
// 5) Final: BN applied to pooled max/min, write [B][128][S]
// =======================================================================
__global__ __launch_bounds__(256) void maxpool2_kernel(const float* __restrict__ mxb,
                                                       const float* __restrict__ mnb,
                                                       float* __restrict__ out) {
    int i = blockIdx.x * 256 + threadIdx.x;       // 128*16384
    int m = i >> 14, bs = i & 16383;
    float sc = g_scale[m], sh = g_shift[m];
    float v = (sc >= 0.0f) ? mxb[i] : mnb[i];
    float r = fmaf(v, sc, sh);
    int b = bs >> 10, s = bs & 1023;
    out[(size_t)BB*3*SS + ((size_t)(b*C3 + m))*SS + s] = fmaxf(r, 0.0f);
}

// 6) new_xyz transpose to [B, 3, S] at output head
__global__ __launch_bounds__(256) void outxyz_kernel(float* __restrict__ out) {
    int i = blockIdx.x * 256 + threadIdx.x;
    if (i >= BB*3*SS) return;
    int s = i & 1023;
    int bd = i >> 10;
    int b = bd / 3, d = bd - b * 3;
    out[i] = g_newxyz[((size_t)b * SS + s) * 3 + d];
}

// =======================================================================
extern "C" void kernel_launch(void* const* d_in, const int* in_sizes, int n_in,
                              void* d_out, int out_size) {
    const float* xyz = (const float*)d_in[0];
    const float* pts = (const float*)d_in[1];
    const float* w0  = (const float*)d_in[2];
    const float* b0  = (const float*)d_in[3];
    const float* g0  = (const float*)d_in[4];
    const float* bt0 = (const float*)d_in[5];
    const float* w1  = (const float*)d_in[6];
    const float* b1  = (const float*)d_in[7];
    const float* g1  = (const float*)d_in[8];
    const float* bt1 = (const float*)d_in[9];
    const float* w2  = (const float*)d_in[10];
    const float* b2  = (const float*)d_in[11];
    const float* g2  = (const float*)d_in[12];
    const float* bt2 = (const float*)d_in[13];
    float* out = (float*)d_out;

    float *pA, *pB, *pT, *pw0, *pw1, *pw2, *pps, *ppq;
    cudaGetSymbolAddress((void**)&pA, g_bufA);
    cudaGetSymbolAddress((void**)&pB, g_bufB);
    cudaGetSymbolAddress((void**)&pT, g_ptsT);
    cudaGetSymbolAddress((void**)&pw0, g_wt0);
    cudaGetSymbolAddress((void**)&pw1, g_wt1);
    cudaGetSymbolAddress((void**)&pw2, g_wt2);
    cudaGetSymbolAddress((void**)&pps, g_psum);
    cudaGetSymbolAddress((void**)&ppq, g_psq);

    const int smemM = (3*NN + 1056 + 16) * 4;            // 53536 B
    const int smem1 = (C0*C1 + C0*256) * 4;              // 85760
    const int smem2 = (C1*C1 + C1*256) * 4;              // 81920
    const int smem3 = (C1*C3 + C1*256) * 4;              // 98304
    cudaFuncSetAttribute(mega_kernel, cudaFuncAttributeMaxDynamicSharedMemorySize, smemM);
    cudaFuncSetAttribute(gemm_kernel<64, 67, false, false>, cudaFuncAttributeMaxDynamicSharedMemorySize, smem1);
    cudaFuncSetAttribute(gemm_kernel<64, 64, true, false>,  cudaFuncAttributeMaxDynamicSharedMemorySize, smem2);
    cudaFuncSetAttribute(gemm_kernel<128, 64, true, true>,  cudaFuncAttributeMaxDynamicSharedMemorySize, smem3);

    reset_kernel<<<1, 32>>>();
    mega_kernel<<<BB + 128, 1024, smemM>>>(xyz, pts, pT, pA);
    wtrans_all_kernel<<<(C0*C1 + C1*C1 + C1*C3 + 255)/256, 256>>>(w0, w1, w2);

    const int nblk = PTOT/256;   // 2048

    // Layer 1: 67 -> 64 (A -> B), 128-thread blocks, tile 64x256
    gemm_kernel<64, 67, false, false><<<nblk, 128, smem1>>>(pA, pB, pw0, b0, pps, ppq, nblk);
    reduce_stats_kernel<<<C1, 256>>>(pps, ppq, g0, bt0, nblk);

    // Layer 2: 64 -> 64 (B -> A), BN+ReLU fused on load
    gemm_kernel<64, 64, true, false><<<nblk, 128, smem2>>>(pB, pA, pw1, b1, pps, ppq, nblk);
    reduce_stats_kernel<<<C1, 256>>>(pps, ppq, g1, bt1, nblk);

    // Layer 3: 64 -> 128 (A -> pooled max/min in B), 256-thread blocks
    gemm_kernel<128, 64, true, true><<<nblk, 256, smem3>>>(pA, pB, pw2, b2, pps, ppq, nblk);
    reduce_stats_kernel<<<C3, 256>>>(pps, ppq, g2, bt2, nblk);

    maxpool2_kernel<<<(C3*BB*SS)/256, 256>>>(pB, pB + (size_t)C3*BB*SS, out);
    outxyz_kernel<<<(BB*3*SS + 255)/256, 256>>>(out);
}